// round 1
// baseline (speedup 1.0000x reference)
#include <cuda_runtime.h>

#define Bsz 4096
#define Lsz 512
#define Msz 17
#define Hsz 17
#define BLOCK_B 28
#define NTHREADS (BLOCK_B * Hsz)   // 476
#define NBLOCKS ((Bsz + BLOCK_B - 1) / BLOCK_B)  // 147

typedef unsigned long long u64;

__device__ __forceinline__ u64 pk2(float a, float b) {
    u64 r; asm("mov.b64 %0, {%1, %2};" : "=l"(r) : "f"(a), "f"(b)); return r;
}
__device__ __forceinline__ void upk2(u64 v, float &a, float &b) {
    asm("mov.b64 {%0, %1}, %2;" : "=f"(a), "=f"(b) : "l"(v));
}
__device__ __forceinline__ void ffma2(u64 &d, u64 a, u64 b) {
    asm("fma.rn.f32x2 %0, %1, %2, %0;" : "+l"(d) : "l"(a), "l"(b));
}
__device__ __forceinline__ float sigm(float z) {
    return __fdividef(1.0f, 1.0f + __expf(-z));
}
__device__ __forceinline__ float tanh_(float z) {
    return __fdividef(2.0f, 1.0f + __expf(-2.0f * z)) - 1.0f;
}

__global__ __launch_bounds__(NTHREADS, 1) void lstm_scan_kernel(
    const float* __restrict__ x,
    const float* __restrict__ Wih,
    const float* __restrict__ Whh,
    const float* __restrict__ bih,
    const float* __restrict__ bhh,
    float* __restrict__ out)
{
    // W_ih packed per (k, j): (row i, row f) and (row g, row o)
    __shared__ u64 wih_if_s[Msz * Hsz];
    __shared__ u64 wih_go_s[Msz * Hsz];
    // double-buffered x and h, stored pre-duplicated as f32x2
    __shared__ u64 xs[2][BLOCK_B][Msz];
    __shared__ u64 hs[2][BLOCK_B][Hsz];

    const int tid = threadIdx.x;
    const int j = tid % Hsz;
    const int y = tid / Hsz;
    const int b = blockIdx.x * BLOCK_B + y;
    const bool act = (b < Bsz);
    const int bb = act ? b : (Bsz - 1);   // clamped for loads

    // ---- fill W_ih smem (289 entries, 476 threads) ----
    if (tid < Msz * Hsz) {
        int k = tid / Hsz, jj = tid % Hsz;
        wih_if_s[tid] = pk2(Wih[jj * Msz + k],            Wih[(Hsz + jj) * Msz + k]);
        wih_go_s[tid] = pk2(Wih[(2 * Hsz + jj) * Msz + k], Wih[(3 * Hsz + jj) * Msz + k]);
    }

    // ---- W_hh in registers, packed ----
    u64 whh_if[Hsz], whh_go[Hsz];
#pragma unroll
    for (int k = 0; k < Hsz; k++) {
        whh_if[k] = pk2(Whh[j * Hsz + k],            Whh[(Hsz + j) * Hsz + k]);
        whh_go[k] = pk2(Whh[(2 * Hsz + j) * Hsz + k], Whh[(3 * Hsz + j) * Hsz + k]);
    }
    const u64 bias_if = pk2(bih[j] + bhh[j],                     bih[Hsz + j] + bhh[Hsz + j]);
    const u64 bias_go = pk2(bih[2 * Hsz + j] + bhh[2 * Hsz + j], bih[3 * Hsz + j] + bhh[3 * Hsz + j]);

    // pointers: element j of row t is xrow[t*Msz]
    const float* xrow = x + (long)bb * Lsz * Msz + j;
    float*       orow = out + (long)bb * Lsz * Hsz + j;

    const long OUT_ELEMS = (long)Bsz * Lsz * Hsz;
    const long H_OFF = OUT_ELEMS;
    const long C_OFF = OUT_ELEMS + (long)Bsz * Hsz;
    const long X_OFF = OUT_ELEMS + 2L * (long)Bsz * Hsz;
    float* xout_row = out + X_OFF + (long)bb * Lsz * Msz + j;

    // prologue: stage t=0
    float x0 = xrow[0];
    if (act) xout_row[0] = x0;           // x passthrough element (b,0,j)
    xs[0][y][j] = pk2(x0, x0);
    hs[0][y][j] = 0ULL;
    float c = 0.0f, hn = 0.0f;
    __syncthreads();

    for (int t = 0; t < Lsz; t++) {
        const int cur = t & 1, nxt = cur ^ 1;

        // prefetch x for t+1 (also serves as the x passthrough write)
        float xnext = 0.0f;
        if (t + 1 < Lsz) xnext = xrow[(t + 1) * Msz];

        u64 aif = bias_if, ago = bias_go;
#pragma unroll
        for (int k = 0; k < Msz; k++) {
            u64 xx = xs[cur][y][k];
            ffma2(aif, wih_if_s[k * Hsz + j], xx);
            ffma2(ago, wih_go_s[k * Hsz + j], xx);
        }
#pragma unroll
        for (int k = 0; k < Hsz; k++) {
            u64 hh = hs[cur][y][k];
            ffma2(aif, whh_if[k], hh);
            ffma2(ago, whh_go[k], hh);
        }

        float zi, zf, zg, zo;
        upk2(aif, zi, zf);
        upk2(ago, zg, zo);
        float ig = sigm(zi);
        float fg = sigm(zf);
        float gg = tanh_(zg);
        float og = sigm(zo);
        c  = fg * c + ig * gg;
        hn = og * tanh_(c);

        if (act) {
            orow[t * Hsz] = hn;
            if (t + 1 < Lsz) xout_row[(t + 1) * Msz] = xnext;
        }
        hs[nxt][y][j] = pk2(hn, hn);
        xs[nxt][y][j] = pk2(xnext, xnext);
        __syncthreads();
    }

    // finals: h_f, c_f
    if (act) {
        out[H_OFF + (long)b * Hsz + j] = hn;
        out[C_OFF + (long)b * Hsz + j] = c;
    }
}

extern "C" void kernel_launch(void* const* d_in, const int* in_sizes, int n_in,
                              void* d_out, int out_size) {
    const float* x   = (const float*)d_in[0];
    const float* Wih = (const float*)d_in[1];
    const float* Whh = (const float*)d_in[2];
    const float* bih = (const float*)d_in[3];
    const float* bhh = (const float*)d_in[4];
    float* out = (float*)d_out;
    (void)in_sizes; (void)n_in; (void)out_size;

    lstm_scan_kernel<<<NBLOCKS, NTHREADS>>>(x, Wih, Whh, bih, bhh, out);
}